// round 4
// baseline (speedup 1.0000x reference)
#include <cuda_runtime.h>
#include <cuda_bf16.h>

#define NN 50000
#define EE 800000
#define DD 128

// ---------------- device scratch (no allocs allowed) ----------------
__device__ float4 g_h[NN * 32];      // current layer input (UNscaled)
__device__ float4 g_agg[NN * 32];    // SpMM output (already * norm_dst)
__device__ int    g_deg[2 * NN];     // [0,NN)=deg_out, [NN,2NN)=deg_in
__device__ float  g_norm_src[NN];
__device__ float  g_norm_dst[NN];
__device__ int    g_row_ptr[NN + 1];
__device__ int    g_cursor[NN];
__device__ int    g_col[EE];         // src ids grouped by dst
__device__ int    g_bsum[64];

// ---------------- setup kernels ----------------
__global__ void k_degree(const int4* __restrict__ src4, const int4* __restrict__ dst4) {
    int t = blockIdx.x * blockDim.x + threadIdx.x;
    if (t < EE / 4) {
        int4 s = src4[t];
        int4 d = dst4[t];
        atomicAdd(&g_deg[s.x], 1); atomicAdd(&g_deg[s.y], 1);
        atomicAdd(&g_deg[s.z], 1); atomicAdd(&g_deg[s.w], 1);
        atomicAdd(&g_deg[NN + d.x], 1); atomicAdd(&g_deg[NN + d.y], 1);
        atomicAdd(&g_deg[NN + d.z], 1); atomicAdd(&g_deg[NN + d.w], 1);
    }
}

__global__ void k_norms() {
    int i = blockIdx.x * blockDim.x + threadIdx.x;
    if (i < NN) {
        int dout = g_deg[i];      if (dout < 1) dout = 1;
        int din  = g_deg[NN + i]; if (din  < 1) din  = 1;
        g_norm_src[i] = rsqrtf((float)dout);
        g_norm_dst[i] = rsqrtf((float)din);
    }
}

// phase 1: per-block exclusive scan of deg_in (1024/block), block sums out
__global__ void k_scan1() {
    __shared__ int warp_sums[32];
    const int tid = threadIdx.x;
    int i = blockIdx.x * 1024 + tid;
    int v = (i < NN) ? g_deg[NN + i] : 0;
    int x = v;
    #pragma unroll
    for (int off = 1; off < 32; off <<= 1) {
        int y = __shfl_up_sync(0xffffffffu, x, off);
        if ((tid & 31) >= off) x += y;
    }
    if ((tid & 31) == 31) warp_sums[tid >> 5] = x;
    __syncthreads();
    if (tid < 32) {
        int w = warp_sums[tid];
        #pragma unroll
        for (int off = 1; off < 32; off <<= 1) {
            int y = __shfl_up_sync(0xffffffffu, w, off);
            if (tid >= off) w += y;
        }
        warp_sums[tid] = w;  // inclusive over warps
    }
    __syncthreads();
    int warp_off = (tid >= 32) ? warp_sums[(tid >> 5) - 1] : 0;
    int incl = x + warp_off;
    if (i < NN) g_row_ptr[i] = incl - v;       // local exclusive
    if (tid == 1023) g_bsum[blockIdx.x] = incl;
}

// phase 2 (merged): each block derives its 1024-group offset from g_bsum
__global__ void k_scan3() {
    __shared__ int s_off;
    const int tid = threadIdx.x;
    const int grp = blockIdx.x >> 2;   // this 256-block lies inside one 1024-group
    if (tid < 32) {
        int a = (tid < grp)      ? g_bsum[tid]      : 0;
        int b = (tid + 32 < grp) ? g_bsum[tid + 32] : 0;
        int s = a + b;
        #pragma unroll
        for (int off = 16; off > 0; off >>= 1)
            s += __shfl_down_sync(0xffffffffu, s, off);
        if (tid == 0) s_off = s;
    }
    __syncthreads();
    int i = blockIdx.x * 256 + tid;
    if (i < NN) {
        int val = g_row_ptr[i] + s_off;
        g_row_ptr[i] = val;
        g_cursor[i]  = val;
    }
    if (i == 0) g_row_ptr[NN] = EE;
}

__global__ void k_fill(const int4* __restrict__ src4, const int4* __restrict__ dst4) {
    int t = blockIdx.x * blockDim.x + threadIdx.x;
    if (t < EE / 4) {
        int4 s = src4[t];
        int4 d = dst4[t];
        g_col[atomicAdd(&g_cursor[d.x], 1)] = s.x;
        g_col[atomicAdd(&g_cursor[d.y], 1)] = s.y;
        g_col[atomicAdd(&g_cursor[d.z], 1)] = s.z;
        g_col[atomicAdd(&g_cursor[d.w], 1)] = s.w;
    }
}

// h0 = emb[batch]   (pure gather; norm_src applied inside SpMM)
__global__ void k_h0(const int* __restrict__ batch, const float4* __restrict__ emb) {
    int idx = blockIdx.x * blockDim.x + threadIdx.x;
    if (idx >= NN * 32) return;
    int i = idx >> 5, q = idx & 31;
    g_h[idx] = emb[(size_t)batch[i] * 32 + q];
}

// ---------------- SpMM: pull-style, warp per dst node, norm fused ----------------
__global__ void k_spmm() {
    int warp = (blockIdx.x * blockDim.x + threadIdx.x) >> 5;
    int lane = threadIdx.x & 31;
    if (warp >= NN) return;
    int beg = g_row_ptr[warp];
    int end = g_row_ptr[warp + 1];
    float4 acc = make_float4(0.f, 0.f, 0.f, 0.f);
    for (int j0 = beg; j0 < end; j0 += 32) {
        int c = 0; float ns = 0.f;
        if (j0 + lane < end) {
            c  = g_col[j0 + lane];
            ns = g_norm_src[c];
        }
        int n = end - j0; if (n > 32) n = 32;
        int t = 0;
        for (; t + 3 < n; t += 4) {
            int s0 = __shfl_sync(0xffffffffu, c, t);
            int s1 = __shfl_sync(0xffffffffu, c, t + 1);
            int s2 = __shfl_sync(0xffffffffu, c, t + 2);
            int s3 = __shfl_sync(0xffffffffu, c, t + 3);
            float w0 = __shfl_sync(0xffffffffu, ns, t);
            float w1 = __shfl_sync(0xffffffffu, ns, t + 1);
            float w2 = __shfl_sync(0xffffffffu, ns, t + 2);
            float w3 = __shfl_sync(0xffffffffu, ns, t + 3);
            float4 v0 = g_h[s0 * 32 + lane];
            float4 v1 = g_h[s1 * 32 + lane];
            float4 v2 = g_h[s2 * 32 + lane];
            float4 v3 = g_h[s3 * 32 + lane];
            acc.x += v0.x * w0 + v1.x * w1 + v2.x * w2 + v3.x * w3;
            acc.y += v0.y * w0 + v1.y * w1 + v2.y * w2 + v3.y * w3;
            acc.z += v0.z * w0 + v1.z * w1 + v2.z * w2 + v3.z * w3;
            acc.w += v0.w * w0 + v1.w * w1 + v2.w * w2 + v3.w * w3;
        }
        for (; t < n; t++) {
            int s = __shfl_sync(0xffffffffu, c, t);
            float w = __shfl_sync(0xffffffffu, ns, t);
            float4 v = g_h[s * 32 + lane];
            acc.x += v.x * w; acc.y += v.y * w; acc.z += v.z * w; acc.w += v.w * w;
        }
    }
    float nd = g_norm_dst[warp];
    acc.x *= nd; acc.y *= nd; acc.z *= nd; acc.w *= nd;
    g_agg[warp * 32 + lane] = acc;
}

// ---------------- TF32 tensor-core GEMM: out = relu(A @ W + b) ----------------
__device__ __forceinline__ unsigned f2tf(float f) {
    unsigned u;
    asm("cvt.rna.tf32.f32 %0, %1;" : "=r"(u) : "f"(f));
    return u;
}

#define AS_STRIDE 68
#define BS_STRIDE 136
#define GEMM_SMEM ((128 * AS_STRIDE + 64 * BS_STRIDE) * 4)

__global__ __launch_bounds__(256, 2) void k_gemm_tf32(
    const float4* __restrict__ A, const float4* __restrict__ W4,
    const float* __restrict__ bias, float2* __restrict__ out, int M)
{
    extern __shared__ unsigned smem[];
    unsigned* As = smem;                       // [128][68]
    unsigned* Bs = smem + 128 * AS_STRIDE;     // [64][136]

    const int tid  = threadIdx.x;
    const int wid  = tid >> 5;
    const int lane = tid & 31;
    const int g = lane >> 2;       // 0..7
    const int c = lane & 3;        // 0..3
    const int wm = (wid & 3) * 32;
    const int wn = (wid >> 2) * 64;
    const int row0 = blockIdx.x * 128;

    float acc[2][8][4];
    #pragma unroll
    for (int i = 0; i < 2; i++)
        #pragma unroll
        for (int j = 0; j < 8; j++)
            #pragma unroll
            for (int k = 0; k < 4; k++) acc[i][j][k] = 0.f;

    for (int k0 = 0; k0 < 128; k0 += 64) {
        #pragma unroll
        for (int l = 0; l < 8; l++) {
            int idx = l * 256 + tid;
            int r = idx >> 4;
            int q = idx & 15;
            float4 v = (row0 + r < M) ? A[(row0 + r) * 32 + (k0 >> 2) + q]
                                      : make_float4(0.f, 0.f, 0.f, 0.f);
            uint4 t = make_uint4(f2tf(v.x), f2tf(v.y), f2tf(v.z), f2tf(v.w));
            *(uint4*)&As[r * AS_STRIDE + q * 4] = t;
        }
        #pragma unroll
        for (int l = 0; l < 8; l++) {
            int idx = l * 256 + tid;
            int k = idx >> 5;
            int nq = idx & 31;
            float4 v = __ldg(&W4[(size_t)(k0 + k) * 32 + nq]);
            uint4 t = make_uint4(f2tf(v.x), f2tf(v.y), f2tf(v.z), f2tf(v.w));
            *(uint4*)&Bs[k * BS_STRIDE + nq * 4] = t;
        }
        __syncthreads();

        #pragma unroll
        for (int kk = 0; kk < 64; kk += 8) {
            unsigned a[2][4];
            #pragma unroll
            for (int mt = 0; mt < 2; mt++) {
                int r = wm + mt * 16 + g;
                a[mt][0] = As[r * AS_STRIDE + kk + c];
                a[mt][1] = As[(r + 8) * AS_STRIDE + kk + c];
                a[mt][2] = As[r * AS_STRIDE + kk + c + 4];
                a[mt][3] = As[(r + 8) * AS_STRIDE + kk + c + 4];
            }
            #pragma unroll
            for (int nt = 0; nt < 8; nt++) {
                unsigned b0 = Bs[(kk + c) * BS_STRIDE + wn + nt * 8 + g];
                unsigned b1 = Bs[(kk + c + 4) * BS_STRIDE + wn + nt * 8 + g];
                #pragma unroll
                for (int mt = 0; mt < 2; mt++) {
                    asm volatile(
                        "mma.sync.aligned.m16n8k8.row.col.f32.tf32.tf32.f32 "
                        "{%0,%1,%2,%3}, {%4,%5,%6,%7}, {%8,%9}, {%0,%1,%2,%3};\n"
                        : "+f"(acc[mt][nt][0]), "+f"(acc[mt][nt][1]),
                          "+f"(acc[mt][nt][2]), "+f"(acc[mt][nt][3])
                        : "r"(a[mt][0]), "r"(a[mt][1]), "r"(a[mt][2]), "r"(a[mt][3]),
                          "r"(b0), "r"(b1));
                }
            }
        }
        __syncthreads();
    }

    const int c2 = c * 2;
    #pragma unroll
    for (int nt = 0; nt < 8; nt++) {
        int col = wn + nt * 8 + c2;
        float bi0 = bias[col], bi1 = bias[col + 1];
        #pragma unroll
        for (int mt = 0; mt < 2; mt++) {
            int r = row0 + wm + mt * 16 + g;
            if (r < M) {
                float2 o;
                o.x = fmaxf(acc[mt][nt][0] + bi0, 0.f);
                o.y = fmaxf(acc[mt][nt][1] + bi1, 0.f);
                out[r * 64 + (col >> 1)] = o;
            }
            int r2 = r + 8;
            if (r2 < M) {
                float2 o;
                o.x = fmaxf(acc[mt][nt][2] + bi0, 0.f);
                o.y = fmaxf(acc[mt][nt][3] + bi1, 0.f);
                out[r2 * 64 + (col >> 1)] = o;
            }
        }
    }
}

// ---------------- launch (single stream, no resource creation) ----------------
extern "C" void kernel_launch(void* const* d_in, const int* in_sizes, int n_in,
                              void* d_out, int out_size)
{
    const int*   batch = (const int*)d_in[0];
    const int*   src   = (const int*)d_in[1];
    const int*   dst   = (const int*)d_in[2];
    const float* emb   = (const float*)d_in[3];
    const float* W1    = (const float*)d_in[4];
    const float* b1    = (const float*)d_in[5];
    const float* W2    = (const float*)d_in[6];
    const float* b2    = (const float*)d_in[7];
    const float* W3    = (const float*)d_in[8];
    const float* b3    = (const float*)d_in[9];
    float* outp = (float*)d_out;

    float4* hbuf;   cudaGetSymbolAddress((void**)&hbuf, g_h);
    float4* aggbuf; cudaGetSymbolAddress((void**)&aggbuf, g_agg);
    int* degp;      cudaGetSymbolAddress((void**)&degp, g_deg);

    cudaFuncSetAttribute(k_gemm_tf32, cudaFuncAttributeMaxDynamicSharedMemorySize,
                         GEMM_SMEM);

    const int scan_blocks = (NN + 1023) / 1024;   // 49

    cudaMemsetAsync(degp, 0, 2 * NN * sizeof(int), 0);
    k_degree<<<(EE / 4 + 255) / 256, 256>>>((const int4*)src, (const int4*)dst);
    k_h0<<<(NN * 32 + 255) / 256, 256>>>(batch, (const float4*)emb);
    k_norms<<<(NN + 255) / 256, 256>>>();
    k_scan1<<<scan_blocks, 1024>>>();
    k_scan3<<<(NN + 255) / 256, 256>>>();
    k_fill<<<(EE / 4 + 255) / 256, 256>>>((const int4*)src, (const int4*)dst);

    const int gemm_grid = (NN + 127) / 128;       // 391
    const int spmm_grid = (NN + 7) / 8;

    // layer 1
    k_spmm<<<spmm_grid, 256>>>();
    k_gemm_tf32<<<gemm_grid, 256, GEMM_SMEM>>>(aggbuf, (const float4*)W1, b1,
                                               (float2*)hbuf, NN);
    // layer 2
    k_spmm<<<spmm_grid, 256>>>();
    k_gemm_tf32<<<gemm_grid, 256, GEMM_SMEM>>>(aggbuf, (const float4*)W2, b2,
                                               (float2*)hbuf, NN);
    // layer 3 -> d_out
    k_spmm<<<spmm_grid, 256>>>();
    k_gemm_tf32<<<gemm_grid, 256, GEMM_SMEM>>>(aggbuf, (const float4*)W3, b3,
                                               (float2*)outp, NN);
}